// round 12
// baseline (speedup 1.0000x reference)
#include <cuda_runtime.h>
#include <cstdint>

// x (8,3,1024,1024) f32 -> out (8,3,512,512) f32
// d_in: [0]=x, [1]=w0 (K0*512), [2]=fov0 (K0*512 i32)  -> dim2 (H, vertical)
//       [3]=w1 (K1*512), [4]=fov1 (K1*512 i32)         -> dim3 (W, horizontal)
//
// R12: WARP-AUTONOMOUS tiles — no __syncthreads anywhere in the hot kernel.
// Each warp owns (bc, oh-tile of 8, 64-output-column octant):
//   vertical streaming resample -> private smem segment of 8 x 144 floats
//   (output window + horizontal halo, edge-clamped), __syncwarp, then the
//   aligned-LDS.128 horizontal fast path. Warps never block on each other,
//   so the per-SM global-load stream stays continuous (kills the barrier
//   convoy that pinned DRAM duty at ~36-40% in R5-R11).

#define BC     24
#define IN_H   1024
#define IN_W   1024
#define OUT_H  512
#define OUT_W  512
#define G      8            // output rows per warp tile
#define NCOL   36           // float4 columns per segment (144 floats)
#define SEGW   (NCOL * 4)   // 144 floats per row

// ---------------------------------------------------------------------------
// Vertical streaming pass for one float4 column of the warp segment.
template<int K>
__device__ __forceinline__
void vert_chunk(const float4* __restrict__ xb, int start, const float* wv,
                int cidx, int seg_start, float* __restrict__ mseg)
{
    constexpr int NROWS = K + 2 * (G - 1);
    const int col4 = min(max(seg_start + cidx, 0), (IN_W / 4) - 1);

    float4 acc[G];
#pragma unroll
    for (int m = 0; m < NROWS; ++m) {
        const float4 v = xb[(size_t)(start + m) * (IN_W / 4) + col4];
#pragma unroll
        for (int i = 0; i < G; ++i) {
            const int j = m - 2 * i;
            if (j == 0) {                       // lazy init: short live range
                acc[i].x = wv[0] * v.x;
                acc[i].y = wv[0] * v.y;
                acc[i].z = wv[0] * v.z;
                acc[i].w = wv[0] * v.w;
            } else if (j > 0 && j < K) {
                acc[i].x += wv[j] * v.x;
                acc[i].y += wv[j] * v.y;
                acc[i].z += wv[j] * v.z;
                acc[i].w += wv[j] * v.w;
            }
        }
        if (m >= K - 1 && ((m - (K - 1)) & 1) == 0) {
            const int i = (m - (K - 1)) / 2;    // retire closed window
            *reinterpret_cast<float4*>(mseg + i * SEGW + 4 * cidx) = acc[i];
        }
    }
}

// ---------------------------------------------------------------------------
// Horizontal fast path: O = (s1 & 3), compile-time. Thread lane produces
// outputs (ow0, ow0+1) for all G rows from 4 aligned float4 LDS per row.
template<int K, int O>
__device__ __forceinline__
void hfast_rows(const float* __restrict__ mseg, int lane,
                const float* __restrict__ wh, float* __restrict__ outp)
{
#pragma unroll
    for (int i = 0; i < G; ++i) {
        const float4* rp = reinterpret_cast<const float4*>(mseg + i * SEGW) + lane;
        float r[16];
#pragma unroll
        for (int q = 0; q < 4; ++q) {
            const float4 v = rp[q];
            r[4 * q + 0] = v.x; r[4 * q + 1] = v.y;
            r[4 * q + 2] = v.z; r[4 * q + 3] = v.w;
        }
        float a0 = 0.f, a1 = 0.f;
#pragma unroll
        for (int j = 0; j < K; ++j) {
            a0 += wh[j] * r[O + j];
            a1 += wh[j] * r[O + 2 + j];
        }
        float2 res; res.x = a0; res.y = a1;
        *reinterpret_cast<float2*>(outp + (size_t)i * OUT_W) = res;
    }
}

// ---------------------------------------------------------------------------
template<int K>
__global__ __launch_bounds__(256, 5)
void fused_warp_kernel(const float* __restrict__ x,
                       const float* __restrict__ w0,
                       const int*   __restrict__ fov0,
                       const float* __restrict__ w1,
                       const int*   __restrict__ fov1,
                       float*       __restrict__ out)
{
    __shared__ __align__(16) float seg[8][G][SEGW];   // 36.9 KB, per-warp

    const int t    = threadIdx.x;
    const int w    = t >> 5;                  // warp = output-column octant
    const int lane = t & 31;
    const int bc   = blockIdx.y;
    const int oh0  = blockIdx.x * G;

    const float4* xb = reinterpret_cast<const float4*>(x + (size_t)bc * IN_H * IN_W);
    float* mseg = &seg[w][0][0];

    // ---- horizontal setup ----------------------------------------------------
    const int s1  = fov1[256] - 512;          // reference interior column
    const int ow0 = 64 * w + 2 * lane;        // this thread's 2 output columns

    float wh[K];
#pragma unroll
    for (int j = 0; j < K; ++j) wh[j] = w1[j * OUT_W + 256];

    int hok = 1;
#pragma unroll
    for (int j = 0; j < K; ++j) {
        const int2   fv = *reinterpret_cast<const int2*>(fov1 + j * OUT_W + ow0);
        const float2 wv2 = *reinterpret_cast<const float2*>(w1  + j * OUT_W + ow0);
        hok &= (fv.x == s1 + 2 * ow0 + j) & (fv.y == s1 + 2 * ow0 + 2 + j);
        hok &= (wv2.x == wh[j]) & (wv2.y == wh[j]);
    }

    const int seg_start = (s1 + 128 * w) >> 2;   // f4 index, floors (may be <0)

    // ---- vertical regularity (warp-scope) -------------------------------------
    const int start = fov0[oh0];
    int flag = 1;
    for (int e = lane; e < K * G; e += 32) {
        const int j = e / G, i = e % G, oh = oh0 + i;
        flag &= (fov0[j * OUT_H + oh] == start + 2 * i + j);
        flag &= (w0  [j * OUT_H + oh] == w0[j * OUT_H + oh0]);
    }
    const int regular = __all_sync(0xffffffffu, flag);

    // ---- Phase 1: vertical resample into this warp's segment ------------------
    if (regular) {
        float wv[K];
#pragma unroll
        for (int j = 0; j < K; ++j) wv[j] = w0[j * OUT_H + oh0];

        vert_chunk<K>(xb, start, wv, lane, seg_start, mseg);        // cols 0..31
        if (lane < 4)
            vert_chunk<K>(xb, start, wv, 32 + lane, seg_start, mseg); // halo cols
    } else {
        // mirror-boundary oh-tile: generic gather fills all 36 f4 columns
        for (int c = lane; c < NCOL; c += 32) {
            const int col4 = min(max(seg_start + c, 0), (IN_W / 4) - 1);
            for (int i = 0; i < G; ++i) {
                const int oh = oh0 + i;
                float ax = 0.f, ay = 0.f, az = 0.f, aw = 0.f;
                for (int j = 0; j < K; ++j) {
                    const int   r = fov0[j * OUT_H + oh];
                    const float wt = w0 [j * OUT_H + oh];
                    const float4 v = xb[(size_t)r * (IN_W / 4) + col4];
                    ax += wt * v.x; ay += wt * v.y; az += wt * v.z; aw += wt * v.w;
                }
                float4 r4; r4.x = ax; r4.y = ay; r4.z = az; r4.w = aw;
                *reinterpret_cast<float4*>(mseg + i * SEGW + 4 * c) = r4;
            }
        }
    }
    __syncwarp();

    // ---- Phase 2: horizontal resample from private segment --------------------
    float* outp = out + ((size_t)bc * OUT_H + oh0) * OUT_W + ow0;

    if (hok) {
        const int o = s1 & 3;                 // uniform across the entire grid
        if      (o == 0) hfast_rows<K, 0>(mseg, lane, wh, outp);
        else if (o == 1) hfast_rows<K, 1>(mseg, lane, wh, outp);
        else if (o == 2) hfast_rows<K, 2>(mseg, lane, wh, outp);
        else             hfast_rows<K, 3>(mseg, lane, wh, outp);
    } else {
        // boundary columns: mirrored indices fold back into this segment
        const int base = 4 * seg_start;
        for (int i = 0; i < G; ++i) {
            float b0 = 0.f, b1 = 0.f;
            for (int j = 0; j < K; ++j) {
                int l0 = fov1[j * OUT_W + ow0]     - base;
                int l1 = fov1[j * OUT_W + ow0 + 1] - base;
                l0 = min(max(l0, 0), SEGW - 1);
                l1 = min(max(l1, 0), SEGW - 1);
                b0 += w1[j * OUT_W + ow0]     * mseg[i * SEGW + l0];
                b1 += w1[j * OUT_W + ow0 + 1] * mseg[i * SEGW + l1];
            }
            float2 res; res.x = b0; res.y = b1;
            *reinterpret_cast<float2*>(outp + (size_t)i * OUT_W) = res;
        }
    }
}

// ---------------------------------------------------------------------------
// Fully generic fallback (runtime K0/K1), parity-split tile.
__global__ __launch_bounds__(256)
void fused_generic_kernel(const float* __restrict__ x,
                          const float* __restrict__ w0,
                          const int*   __restrict__ fov0,
                          const float* __restrict__ w1,
                          const int*   __restrict__ fov1,
                          float*       __restrict__ out,
                          int K0, int K1)
{
    __shared__ float tile[G][IN_W];
    const int t   = threadIdx.x;
    const int bc  = blockIdx.y;
    const int oh0 = blockIdx.x * G;
    const float4* xb = reinterpret_cast<const float4*>(x + (size_t)bc * IN_H * IN_W);

    for (int i = 0; i < G; ++i) {
        const int oh = oh0 + i;
        float ax = 0.f, ay = 0.f, az = 0.f, aw = 0.f;
        for (int j = 0; j < K0; ++j) {
            const int   r = fov0[j * OUT_H + oh];
            const float wt = w0 [j * OUT_H + oh];
            const float4 v = xb[(size_t)r * (IN_W / 4) + t];
            ax += wt * v.x; ay += wt * v.y; az += wt * v.z; aw += wt * v.w;
        }
        float2 e; e.x = ax; e.y = az;
        float2 o; o.x = ay; o.y = aw;
        reinterpret_cast<float2*>(tile[i])[t]       = e;
        reinterpret_cast<float2*>(tile[i] + 512)[t] = o;
    }
    __syncthreads();

    float a0[G], a1[G];
#pragma unroll
    for (int i = 0; i < G; ++i) { a0[i] = 0.f; a1[i] = 0.f; }
    for (int j = 0; j < K1; ++j) {
        const float w_a = w1  [j * OUT_W + t];
        const float w_b = w1  [j * OUT_W + t + 256];
        const int   f_a = fov1[j * OUT_W + t];
        const int   f_b = fov1[j * OUT_W + t + 256];
        const int p_a = (f_a >> 1) + ((f_a & 1) << 9);
        const int p_b = (f_b >> 1) + ((f_b & 1) << 9);
#pragma unroll
        for (int i = 0; i < G; ++i) {
            a0[i] += w_a * tile[i][p_a];
            a1[i] += w_b * tile[i][p_b];
        }
    }
#pragma unroll
    for (int i = 0; i < G; ++i) {
        float* orow = out + ((size_t)bc * OUT_H + oh0 + i) * OUT_W;
        orow[t]       = a0[i];
        orow[t + 256] = a1[i];
    }
}

// ---------------------------------------------------------------------------

extern "C" void kernel_launch(void* const* d_in, const int* in_sizes, int n_in,
                              void* d_out, int out_size)
{
    const float* x    = (const float*)d_in[0];
    const float* w0   = (const float*)d_in[1];
    const int*   fov0 = (const int*)  d_in[2];
    const float* w1   = (const float*)d_in[3];
    const int*   fov1 = (const int*)  d_in[4];
    float*       out  = (float*)d_out;

    const int K0 = in_sizes[1] / OUT_H;   // vertical taps
    const int K1 = in_sizes[3] / OUT_W;   // horizontal taps

    dim3 grid(OUT_H / G, BC);

    if (K0 == K1) {
        switch (K0) {
        case 6:  fused_warp_kernel< 6><<<grid, 256>>>(x, w0, fov0, w1, fov1, out); return;
        case 7:  fused_warp_kernel< 7><<<grid, 256>>>(x, w0, fov0, w1, fov1, out); return;
        case 8:  fused_warp_kernel< 8><<<grid, 256>>>(x, w0, fov0, w1, fov1, out); return;
        case 9:  fused_warp_kernel< 9><<<grid, 256>>>(x, w0, fov0, w1, fov1, out); return;
        case 10: fused_warp_kernel<10><<<grid, 256>>>(x, w0, fov0, w1, fov1, out); return;
        case 11: fused_warp_kernel<11><<<grid, 256>>>(x, w0, fov0, w1, fov1, out); return;
        case 12: fused_warp_kernel<12><<<grid, 256>>>(x, w0, fov0, w1, fov1, out); return;
        default: break;
        }
    }
    fused_generic_kernel<<<grid, 256>>>(x, w0, fov0, w1, fov1, out, K0, K1);
}

// round 13
// speedup vs baseline: 1.1975x; 1.1975x over previous
#include <cuda_runtime.h>
#include <cstdint>

// x (8,3,1024,1024) f32 -> out (8,3,512,512) f32
// d_in: [0]=x, [1]=w0 (K0*512), [2]=fov0 (K0*512 i32)  -> dim2 (H, vertical)
//       [3]=w1 (K1*512), [4]=fov1 (K1*512 i32)         -> dim3 (W, horizontal)
//
// R13: R8/R11 skeleton, one clean change: EXPLICIT PREFETCH QUEUE (depth 3)
// in the vertical streaming loop, guaranteeing MLP>=3 per warp regardless of
// ptxas scheduling (the mid-loop STS retirement + register reuse was likely
// pinning MLP~2 -> 3.1TB/s ceiling). Also: horizontal regularity check and
// its global loads hoisted BEFORE phase 1 (overlap LDG latency); wh reloaded
// after the barrier (L1 hits) to keep peak registers ~50 (5 blocks/SM).

#define BC     24
#define IN_H   1024
#define IN_W   1024
#define OUT_H  512
#define OUT_W  512
#define G      8            // output rows per block
#define PADW   16           // tile row padding (floats) each side
#define TROW   (IN_W + 2 * PADW)
#define PF     3            // prefetch depth (register queue)

// ---------------------------------------------------------------------------
template<int K, int O>
__device__ __forceinline__
void hfast_rows(const float tile[G][TROW], int wstart,
                const float* __restrict__ wh,
                float* __restrict__ outp)
{
    constexpr int NQ = (K + 8) / 4;
#pragma unroll
    for (int i = 0; i < G; ++i) {
        const float4* rp = reinterpret_cast<const float4*>(tile[i] + PADW) + wstart;
        float r[NQ * 4];
#pragma unroll
        for (int q = 0; q < NQ; ++q) {
            const float4 v = rp[q];
            r[4 * q + 0] = v.x; r[4 * q + 1] = v.y;
            r[4 * q + 2] = v.z; r[4 * q + 3] = v.w;
        }
        float a0 = 0.f, a1 = 0.f;
#pragma unroll
        for (int j = 0; j < K; ++j) {
            a0 += wh[j] * r[O + j];
            a1 += wh[j] * r[O + 2 + j];
        }
        float2 res; res.x = a0; res.y = a1;
        *reinterpret_cast<float2*>(outp + (size_t)i * OUT_W) = res;
    }
}

// ---------------------------------------------------------------------------
template<int K>
__global__ __launch_bounds__(256, 5)
void fused_stream_kernel(const float* __restrict__ x,
                         const float* __restrict__ w0,
                         const int*   __restrict__ fov0,
                         const float* __restrict__ w1,
                         const int*   __restrict__ fov1,
                         float*       __restrict__ out)
{
    __shared__ float tile[G][TROW];              // ~33 KB

    const int t   = threadIdx.x;                 // 0..255
    const int bc  = blockIdx.y;
    const int oh0 = blockIdx.x * G;

    const float4* xb = reinterpret_cast<const float4*>(x + (size_t)bc * IN_H * IN_W);

    // ---- hoisted horizontal regularity check (overlaps phase-1 latency) ----
    const int ow0 = 2 * t;
    const int s1  = fov1[256] - 512;             // reference interior column
    int hok = 1;
#pragma unroll
    for (int j = 0; j < K; ++j) {
        const float wr = w1[j * OUT_W + 256];
        const int2   fv = *reinterpret_cast<const int2*>(fov1 + j * OUT_W + ow0);
        const float2 wv2 = *reinterpret_cast<const float2*>(w1  + j * OUT_W + ow0);
        hok &= (fv.x == s1 + 2 * ow0 + j) & (fv.y == s1 + 2 * ow0 + 2 + j);
        hok &= (wv2.x == wr) & (wv2.y == wr);
    }

    // ---- vertical regularity: fov0[j][oh0+i] == start + 2i + j, w0 oh-invar.
    const int start = fov0[oh0];
    int flag = 1;
    if (t < K * G) {
        const int j  = t / G;
        const int i  = t % G;
        const int oh = oh0 + i;
        flag  = (fov0[j * OUT_H + oh] == start + 2 * i + j);
        flag &= (w0  [j * OUT_H + oh] == w0[j * OUT_H + oh0]);
    }
    const int regular = __syncthreads_and(flag);

    if (regular) {
        // ---------- Phase 1a: streaming with explicit depth-PF prefetch -----
        constexpr int NROWS = K + 2 * (G - 1);   // 22 for K=8

        float wv[K];
#pragma unroll
        for (int j = 0; j < K; ++j) wv[j] = w0[j * OUT_H + oh0];

        const float4* xrow = xb + (size_t)start * (IN_W / 4) + t;
        const int stride4 = IN_W / 4;

        float4 vq[PF];
#pragma unroll
        for (int p = 0; p < PF; ++p) vq[p] = xrow[(size_t)p * stride4];

        float4 acc[G];
#pragma unroll
        for (int m = 0; m < NROWS; ++m) {
            const float4 v = vq[m % PF];
            if (m + PF < NROWS)                  // compile-time pruned
                vq[m % PF] = xrow[(size_t)(m + PF) * stride4];
#pragma unroll
            for (int i = 0; i < G; ++i) {
                const int j = m - 2 * i;
                if (j == 0) {                    // lazy init: short live range
                    acc[i].x = wv[0] * v.x;
                    acc[i].y = wv[0] * v.y;
                    acc[i].z = wv[0] * v.z;
                    acc[i].w = wv[0] * v.w;
                } else if (j > 0 && j < K) {
                    acc[i].x += wv[j] * v.x;
                    acc[i].y += wv[j] * v.y;
                    acc[i].z += wv[j] * v.z;
                    acc[i].w += wv[j] * v.w;
                }
            }
            if (m >= K - 1 && ((m - (K - 1)) & 1) == 0) {
                const int i = (m - (K - 1)) / 2; // retire closed window
                reinterpret_cast<float4*>(tile[i] + PADW)[t] = acc[i];
            }
        }
    } else {
        // ---------- Phase 1b: generic gather (boundary blocks) ----------
        for (int i = 0; i < G; ++i) {
            const int oh = oh0 + i;
            float ax = 0.f, ay = 0.f, az = 0.f, aw = 0.f;
            for (int j = 0; j < K; ++j) {
                const int   r = fov0[j * OUT_H + oh];
                const float w = w0  [j * OUT_H + oh];
                const float4 v = xb[(size_t)r * (IN_W / 4) + t];
                ax += w * v.x; ay += w * v.y; az += w * v.z; aw += w * v.w;
            }
            float4 r4; r4.x = ax; r4.y = ay; r4.z = az; r4.w = aw;
            reinterpret_cast<float4*>(tile[i] + PADW)[t] = r4;
        }
    }
    __syncthreads();

    // ---------------- Phase 2: horizontal resample ---------------------------
    float wh[K];                                 // reload (L1 hits), saves regs
#pragma unroll
    for (int j = 0; j < K; ++j) wh[j] = w1[j * OUT_W + 256];

    float* outp = out + ((size_t)bc * OUT_H + oh0) * OUT_W + ow0;

    if (hok) {
        const int o      = s1 & 3;               // uniform across entire grid
        const int wstart = (s1 + 4 * t) >> 2;
        if      (o == 0) hfast_rows<K, 0>(tile, wstart, wh, outp);
        else if (o == 1) hfast_rows<K, 1>(tile, wstart, wh, outp);
        else if (o == 2) hfast_rows<K, 2>(tile, wstart, wh, outp);
        else             hfast_rows<K, 3>(tile, wstart, wh, outp);
    } else {
        for (int i = 0; i < G; ++i) {
            float b0 = 0.f, b1 = 0.f;
            for (int j = 0; j < K; ++j) {
                b0 += w1[j * OUT_W + ow0]     * tile[i][PADW + fov1[j * OUT_W + ow0]];
                b1 += w1[j * OUT_W + ow0 + 1] * tile[i][PADW + fov1[j * OUT_W + ow0 + 1]];
            }
            float2 res; res.x = b0; res.y = b1;
            *reinterpret_cast<float2*>(outp + (size_t)i * OUT_W) = res;
        }
    }
}

// ---------------------------------------------------------------------------
// Fully generic fallback (runtime K0/K1), parity-split tile.
__global__ __launch_bounds__(256)
void fused_generic_kernel(const float* __restrict__ x,
                          const float* __restrict__ w0,
                          const int*   __restrict__ fov0,
                          const float* __restrict__ w1,
                          const int*   __restrict__ fov1,
                          float*       __restrict__ out,
                          int K0, int K1)
{
    __shared__ float tile[G][IN_W];
    const int t   = threadIdx.x;
    const int bc  = blockIdx.y;
    const int oh0 = blockIdx.x * G;
    const float4* xb = reinterpret_cast<const float4*>(x + (size_t)bc * IN_H * IN_W);

    for (int i = 0; i < G; ++i) {
        const int oh = oh0 + i;
        float ax = 0.f, ay = 0.f, az = 0.f, aw = 0.f;
        for (int j = 0; j < K0; ++j) {
            const int   r = fov0[j * OUT_H + oh];
            const float w = w0  [j * OUT_H + oh];
            const float4 v = xb[(size_t)r * (IN_W / 4) + t];
            ax += w * v.x; ay += w * v.y; az += w * v.z; aw += w * v.w;
        }
        float2 e; e.x = ax; e.y = az;
        float2 o; o.x = ay; o.y = aw;
        reinterpret_cast<float2*>(tile[i])[t]       = e;
        reinterpret_cast<float2*>(tile[i] + 512)[t] = o;
    }
    __syncthreads();

    float a0[G], a1[G];
#pragma unroll
    for (int i = 0; i < G; ++i) { a0[i] = 0.f; a1[i] = 0.f; }
    for (int j = 0; j < K1; ++j) {
        const float w_a = w1  [j * OUT_W + t];
        const float w_b = w1  [j * OUT_W + t + 256];
        const int   f_a = fov1[j * OUT_W + t];
        const int   f_b = fov1[j * OUT_W + t + 256];
        const int p_a = (f_a >> 1) + ((f_a & 1) << 9);
        const int p_b = (f_b >> 1) + ((f_b & 1) << 9);
#pragma unroll
        for (int i = 0; i < G; ++i) {
            a0[i] += w_a * tile[i][p_a];
            a1[i] += w_b * tile[i][p_b];
        }
    }
#pragma unroll
    for (int i = 0; i < G; ++i) {
        float* orow = out + ((size_t)bc * OUT_H + oh0 + i) * OUT_W;
        orow[t]       = a0[i];
        orow[t + 256] = a1[i];
    }
}

// ---------------------------------------------------------------------------

extern "C" void kernel_launch(void* const* d_in, const int* in_sizes, int n_in,
                              void* d_out, int out_size)
{
    const float* x    = (const float*)d_in[0];
    const float* w0   = (const float*)d_in[1];
    const int*   fov0 = (const int*)  d_in[2];
    const float* w1   = (const float*)d_in[3];
    const int*   fov1 = (const int*)  d_in[4];
    float*       out  = (float*)d_out;

    const int K0 = in_sizes[1] / OUT_H;   // vertical taps
    const int K1 = in_sizes[3] / OUT_W;   // horizontal taps

    dim3 grid(OUT_H / G, BC);

    if (K0 == K1) {
        switch (K0) {
        case 6:  fused_stream_kernel< 6><<<grid, 256>>>(x, w0, fov0, w1, fov1, out); return;
        case 7:  fused_stream_kernel< 7><<<grid, 256>>>(x, w0, fov0, w1, fov1, out); return;
        case 8:  fused_stream_kernel< 8><<<grid, 256>>>(x, w0, fov0, w1, fov1, out); return;
        case 9:  fused_stream_kernel< 9><<<grid, 256>>>(x, w0, fov0, w1, fov1, out); return;
        case 10: fused_stream_kernel<10><<<grid, 256>>>(x, w0, fov0, w1, fov1, out); return;
        case 11: fused_stream_kernel<11><<<grid, 256>>>(x, w0, fov0, w1, fov1, out); return;
        case 12: fused_stream_kernel<12><<<grid, 256>>>(x, w0, fov0, w1, fov1, out); return;
        default: break;
        }
    }
    fused_generic_kernel<<<grid, 256>>>(x, w0, fov0, w1, fov1, out, K0, K1);
}